// round 1
// baseline (speedup 1.0000x reference)
#include <cuda_runtime.h>

// CostVolume: out[bh, w, d] = (1/64) * sum_c L[bh,w,c] * R[bh, w-d-1, c],
// zero where w-d-1 < 0.  B*H = derived from in_sizes, W=512, C=64, D=64.

namespace {
constexpr int Wd   = 512;
constexpr int Cd   = 64;
constexpr int Dd   = 64;
constexpr int WT   = 128;          // w-tile per block
constexpr int RROWS = WT + 64;     // 192 source rows (halo of 64 on the left)
constexpr int SLP  = WT + 4;       // 132: pitch/4 = 33 == 1 (mod 8)  -> conflict-free
constexpr int SRP  = RROWS + 4;    // 196: pitch/4 = 49 == 1 (mod 8)
constexpr int SMEM_BYTES = (Cd * SLP + Cd * SRP) * 4;   // 83,968 B
}

__global__ __launch_bounds__(128, 2)
void cost_volume_kernel(const float* __restrict__ left,
                        const float* __restrict__ right,
                        float* __restrict__ out) {
    extern __shared__ float sm[];
    float* Ls = sm;                 // [Cd][SLP]   (transposed: [c][w_local])
    float* Rs = sm + Cd * SLP;      // [Cd][SRP]   (transposed: [c][src_local])

    const int wtile = blockIdx.x;
    const int bh    = blockIdx.y;
    const int w0    = wtile * WT;

    const float* lrow = left  + (size_t)bh * Wd * Cd;
    const float* rrow = right + (size_t)bh * Wd * Cd;

    const int tid = threadIdx.x;

    // ---------------- fill: global [row][c] -> smem [c][row] ----------------
    {
        const int c = tid & 63;     // 0..63
        const int g = tid >> 6;     // 0..1
        // L rows (global w = w0 + r), always in range
        for (int r0 = g * 4; r0 < WT; r0 += 8) {
            float4 v;
            v.x = lrow[(w0 + r0 + 0) * Cd + c];
            v.y = lrow[(w0 + r0 + 1) * Cd + c];
            v.z = lrow[(w0 + r0 + 2) * Cd + c];
            v.w = lrow[(w0 + r0 + 3) * Cd + c];
            *(float4*)&Ls[c * SLP + r0] = v;
        }
        // R rows: src_global = w0 - 64 + r, clamped (values for src<0 are
        // masked to 0 in the epilogue, so any finite value is fine)
        for (int r0 = g * 4; r0 < RROWS; r0 += 8) {
            const int s = w0 - 64 + r0;
            float4 v;
            v.x = rrow[max(s + 0, 0) * Cd + c];
            v.y = rrow[max(s + 1, 0) * Cd + c];
            v.z = rrow[max(s + 2, 0) * Cd + c];
            v.w = rrow[max(s + 3, 0) * Cd + c];
            *(float4*)&Rs[c * SRP + r0] = v;
        }
    }
    __syncthreads();

    // ---------------- compute: 8w x 8d register tile per thread -------------
    const int tx = tid & 7;          // d-group: d = tx*8 + j
    const int ty = tid >> 3;         // w-group: w_local = ty*8 + i   (0..15)
    const int lb = ty * 8;
    const int rb = 56 + ty * 8 - tx * 8;   // src_local for (i-j) = -7; in [0,120]

    float acc[8][8];
#pragma unroll
    for (int i = 0; i < 8; i++)
#pragma unroll
        for (int j = 0; j < 8; j++) acc[i][j] = 0.0f;

#pragma unroll 4
    for (int c = 0; c < Cd; c++) {
        float a[8];
        float r[16];
        *(float4*)&a[0] = *(const float4*)&Ls[c * SLP + lb];
        *(float4*)&a[4] = *(const float4*)&Ls[c * SLP + lb + 4];
        *(float4*)&r[0]  = *(const float4*)&Rs[c * SRP + rb];
        *(float4*)&r[4]  = *(const float4*)&Rs[c * SRP + rb + 4];
        *(float4*)&r[8]  = *(const float4*)&Rs[c * SRP + rb + 8];
        *(float4*)&r[12] = *(const float4*)&Rs[c * SRP + rb + 12];
#pragma unroll
        for (int i = 0; i < 8; i++)
#pragma unroll
            for (int j = 0; j < 8; j++)
                acc[i][j] += a[i] * r[i - j + 7];   // src_local = rb + i - j + 7
    }

    // ---------------- epilogue: scale, mask src<0, vector store --------------
    const float scale = 1.0f / 64.0f;
#pragma unroll
    for (int i = 0; i < 8; i++) {
        const int wg = w0 + ty * 8 + i;                 // global w
        float* op = out + ((size_t)bh * Wd + wg) * Dd + tx * 8;
        float v[8];
#pragma unroll
        for (int j = 0; j < 8; j++) {
            const int src = wg - (tx * 8 + j) - 1;
            v[j] = (src >= 0) ? acc[i][j] * scale : 0.0f;
        }
        *(float4*)(op)     = make_float4(v[0], v[1], v[2], v[3]);
        *(float4*)(op + 4) = make_float4(v[4], v[5], v[6], v[7]);
    }
}

extern "C" void kernel_launch(void* const* d_in, const int* in_sizes, int n_in,
                              void* d_out, int out_size) {
    const float* left  = (const float*)d_in[0];
    const float* right = (const float*)d_in[1];
    float* out = (float*)d_out;

    const int BH = in_sizes[0] / (Wd * Cd);   // 1024 for the given shapes

    cudaFuncSetAttribute(cost_volume_kernel,
                         cudaFuncAttributeMaxDynamicSharedMemorySize, SMEM_BYTES);

    dim3 grid(Wd / WT, BH, 1);
    cost_volume_kernel<<<grid, 128, SMEM_BYTES>>>(left, right, out);
}

// round 2
// speedup vs baseline: 1.7797x; 1.7797x over previous
#include <cuda_runtime.h>

// CostVolume: out[bh, w, d] = (1/64) * sum_c L[bh,w,c] * R[bh, w-d-1, c],
// zero where w-d-1 < 0.   W=512, C=64, D=64, BH derived.
//
// Design: per block 128 w-tile x 64 d, c split in two 32-channel phases
// (smem 42KB -> 4 blocks/SM).  Bank-conflict-free via per-thread channel
// rotation (c' = ci ^ tx) + 16B-chunk XOR swizzle.  Inner product uses
// packed fp32x2 FMA (fma.rn.f32x2, sm_100+).

typedef unsigned long long ull;

namespace {
constexpr int Wd    = 512;
constexpr int Cd    = 64;
constexpr int Dd    = 64;
constexpr int WT    = 128;          // w-tile per block
constexpr int RROWS = WT + 64;      // 192 source rows (left halo 64)
constexpr int CP    = 32;           // channels per phase
constexpr int SLP   = WT + 4;       // 132 floats: 132 % 32 == 4 (needed by swizzle math)
constexpr int SRP   = RROWS + 4;    // 196 floats: 196 % 32 == 4
constexpr int SMEM_FLOATS = CP * SLP + CP * SRP;   // 10496 floats = 41,984 B
}

__device__ __forceinline__ ull pack2(float lo, float hi) {
    ull r;
    asm("mov.b64 %0, {%1, %2};" : "=l"(r) : "f"(lo), "f"(hi));
    return r;
}
// pair {hi(x), lo(y)} -> the "odd-offset" float pair
__device__ __forceinline__ ull mid2(ull x, ull y) {
    ull r;
    asm("{\n\t.reg .b32 a,b,c,d;\n\t"
        "mov.b64 {a,b}, %1;\n\t"
        "mov.b64 {c,d}, %2;\n\t"
        "mov.b64 %0, {b,c};\n\t}"
        : "=l"(r) : "l"(x), "l"(y));
    return r;
}
__device__ __forceinline__ void ffma2(ull& d, ull a, ull b) {
    asm("fma.rn.f32x2 %0, %1, %2, %0;" : "+l"(d) : "l"(a), "l"(b));
}
__device__ __forceinline__ void unpack2(ull v, float& lo, float& hi) {
    asm("mov.b64 {%0, %1}, %2;" : "=f"(lo), "=f"(hi) : "l"(v));
}

__global__ __launch_bounds__(128, 4)
void cost_volume_kernel(const float* __restrict__ left,
                        const float* __restrict__ right,
                        float* __restrict__ out) {
    __shared__ float sm[SMEM_FLOATS];
    float* Ls = sm;                // [CP][SLP], chunk-swizzled
    float* Rs = sm + CP * SLP;     // [CP][SRP], chunk-swizzled

    const int tid = threadIdx.x;
    const int w0  = blockIdx.x * WT;
    const int bh  = blockIdx.y;
    const float* lrow = left  + (size_t)bh * Wd * Cd;
    const float* rrow = right + (size_t)bh * Wd * Cd;

    // compute mapping: 8w x 8d register tile
    const int tx = tid & 7;            // d-group: d = tx*8 + j
    const int ty = tid >> 3;           // w-group: w_local = ty*8 + i
    const int lb = ty * 8;
    const int rb = 56 + 8 * (ty - tx); // window start, in [0, 176]

    // fill mapping
    const int fc   = tid & 31;         // channel within phase
    const int fg   = tid >> 5;         // row group 0..3
    const int fswz = 2 * (fc >> 3);    // chunk swizzle for this channel

    ull p[4][8];                       // acc pairs: lo=acc[2ii][j], hi=acc[2ii+1][j]
#pragma unroll
    for (int ii = 0; ii < 4; ii++)
#pragma unroll
        for (int j = 0; j < 8; j++) p[ii][j] = 0ull;

    for (int ph = 0; ph < 2; ph++) {
        const int cb = ph * CP;
        if (ph) __syncthreads();       // previous compute done before refill

        // ---- fill: gmem [row][c] -> smem [c][chunk-swizzled row] ----
        for (int r0 = 4 * fg; r0 < WT; r0 += 16) {
            const float* src = lrow + (size_t)(w0 + r0) * Cd + cb + fc;
            float4 v;
            v.x = src[0]; v.y = src[Cd]; v.z = src[2 * Cd]; v.w = src[3 * Cd];
            *(float4*)&Ls[fc * SLP + 4 * ((r0 >> 2) ^ fswz)] = v;
        }
        for (int r0 = 4 * fg; r0 < RROWS; r0 += 16) {
            const int s = w0 - 64 + r0;
            float4 v;
            v.x = rrow[(size_t)max(s + 0, 0) * Cd + cb + fc];
            v.y = rrow[(size_t)max(s + 1, 0) * Cd + cb + fc];
            v.z = rrow[(size_t)max(s + 2, 0) * Cd + cb + fc];
            v.w = rrow[(size_t)max(s + 3, 0) * Cd + cb + fc];
            *(float4*)&Rs[fc * SRP + 4 * ((r0 >> 2) ^ fswz)] = v;
        }
        __syncthreads();

        // ---- compute 32 channels (rotated per-thread: c' = ci ^ tx) ----
#pragma unroll 8
        for (int ci = 0; ci < CP; ci++) {
            const int cp  = ci ^ tx;          // bijection over 0..31
            const int swz = 2 * (cp >> 3);    // == 2*(ci>>3)
            const float* lsrc = &Ls[cp * SLP];
            const float* rsrc = &Rs[cp * SRP];

            ull la[4];                         // a pairs {a[2ii], a[2ii+1]}
            {
                const int c0 = ((lb >> 2) + 0) ^ swz;
                const int c1 = ((lb >> 2) + 1) ^ swz;
                *(ulonglong2*)&la[0] = *(const ulonglong2*)&lsrc[4 * c0];
                *(ulonglong2*)&la[2] = *(const ulonglong2*)&lsrc[4 * c1];
            }
            ull rr[8];                         // even pairs {r[2k], r[2k+1]}
            {
                const int c0 = ((rb >> 2) + 0) ^ swz;
                const int c1 = ((rb >> 2) + 1) ^ swz;
                const int c2 = ((rb >> 2) + 2) ^ swz;
                const int c3 = ((rb >> 2) + 3) ^ swz;
                *(ulonglong2*)&rr[0] = *(const ulonglong2*)&rsrc[4 * c0];
                *(ulonglong2*)&rr[2] = *(const ulonglong2*)&rsrc[4 * c1];
                *(ulonglong2*)&rr[4] = *(const ulonglong2*)&rsrc[4 * c2];
                *(ulonglong2*)&rr[6] = *(const ulonglong2*)&rsrc[4 * c3];
            }
            ull so[7];                         // odd pairs {r[2k+1], r[2k+2]}
#pragma unroll
            for (int k = 0; k < 7; k++) so[k] = mid2(rr[k], rr[k + 1]);

#pragma unroll
            for (int ii = 0; ii < 4; ii++)
#pragma unroll
                for (int j = 0; j < 8; j++) {
                    const int k = 2 * ii - j + 7;          // 0..13
                    const ull b = (k & 1) ? so[(k - 1) >> 1] : rr[k >> 1];
                    ffma2(p[ii][j], la[ii], b);
                }
        }
    }

    // ---- epilogue: unpack, scale, mask src<0, vector store ----
    const float scale = 1.0f / 64.0f;
#pragma unroll
    for (int ii = 0; ii < 4; ii++) {
        float a0[8], a1[8];
#pragma unroll
        for (int j = 0; j < 8; j++) unpack2(p[ii][j], a0[j], a1[j]);
#pragma unroll
        for (int h = 0; h < 2; h++) {
            const float* acc = h ? a1 : a0;
            const int wg = w0 + lb + 2 * ii + h;       // global w
            float* op = out + ((size_t)bh * Wd + wg) * Dd + tx * 8;
            float v[8];
#pragma unroll
            for (int j = 0; j < 8; j++) {
                const int src = wg - (tx * 8 + j) - 1;
                v[j] = (src >= 0) ? acc[j] * scale : 0.0f;
            }
            *(float4*)(op)     = make_float4(v[0], v[1], v[2], v[3]);
            *(float4*)(op + 4) = make_float4(v[4], v[5], v[6], v[7]);
        }
    }
}

extern "C" void kernel_launch(void* const* d_in, const int* in_sizes, int n_in,
                              void* d_out, int out_size) {
    const float* left  = (const float*)d_in[0];
    const float* right = (const float*)d_in[1];
    float* outp = (float*)d_out;

    const int BH = in_sizes[0] / (Wd * Cd);
    dim3 grid(Wd / WT, BH, 1);
    cost_volume_kernel<<<grid, 128>>>(left, right, outp);
}